// round 3
// baseline (speedup 1.0000x reference)
#include <cuda_runtime.h>
#include <cuda_fp16.h>

#define BB   32
#define NIN  2048
#define DIN  16
#define JJ   64
#define CC   32
#define NITR 5

#define PLANE 4194304u   // JJ*NIN*CC, elements per batch-plane of g_uhat

// 256 MB fp16 scratch for u_hat, layout [b][j][i][c]
__device__ __half g_uhat[(size_t)BB * JJ * NIN * CC];

// ---------- packed f32x2 helpers (FFMA2 is PTX-only on sm_103a) ----------
__device__ __forceinline__ unsigned long long pack2(float x, float y) {
    unsigned long long r;
    asm("mov.b64 %0, {%1, %2};" : "=l"(r) : "f"(x), "f"(y));
    return r;
}
__device__ __forceinline__ void unpack2(unsigned long long v, float& x, float& y) {
    asm("mov.b64 {%0, %1}, %2;" : "=f"(x), "=f"(y) : "l"(v));
}
__device__ __forceinline__ unsigned long long ffma2(unsigned long long a,
                                                    unsigned long long b,
                                                    unsigned long long c) {
    unsigned long long d;
    asm("fma.rn.f32x2 %0, %1, %2, %3;" : "=l"(d) : "l"(a), "l"(b), "l"(c));
    return d;
}

// =====================================================================
// Phase 1: u_hat[b,i,j,c] = sum_d u[b,i,d] * W[i,j,c,d]   (fp32 -> fp16)
// One block per input capsule i; 256 threads; thread owns 8 jc columns.
// Register-bounded: accumulate 8 batch-pairs (16 regs) at a time.
// =====================================================================
__global__ __launch_bounds__(256) void uhat_kernel(const float* __restrict__ x,
                                                   const float* __restrict__ W) {
    const int i   = blockIdx.x;
    const int tid = threadIdx.x;

    __shared__ float u_s[16 * 32];   // [d][b]
    for (int k = tid; k < 512; k += 256) {
        int b = k >> 4, d = k & 15;
        u_s[d * 32 + b] = x[((size_t)b * NIN + i) * DIN + d];
    }
    __syncthreads();

    const float* wbase = W + (size_t)i * (JJ * CC * DIN);

    #pragma unroll 1
    for (int r = 0; r < 8; ++r) {
        const int jc = (r << 8) + tid;
        const float4* wr = reinterpret_cast<const float4*>(wbase + jc * DIN);
        float4 w0 = wr[0], w1 = wr[1], w2 = wr[2], w3 = wr[3];
        unsigned long long wd2[16];
        wd2[0]  = pack2(w0.x, w0.x); wd2[1]  = pack2(w0.y, w0.y);
        wd2[2]  = pack2(w0.z, w0.z); wd2[3]  = pack2(w0.w, w0.w);
        wd2[4]  = pack2(w1.x, w1.x); wd2[5]  = pack2(w1.y, w1.y);
        wd2[6]  = pack2(w1.z, w1.z); wd2[7]  = pack2(w1.w, w1.w);
        wd2[8]  = pack2(w2.x, w2.x); wd2[9]  = pack2(w2.y, w2.y);
        wd2[10] = pack2(w2.z, w2.z); wd2[11] = pack2(w2.w, w2.w);
        wd2[12] = pack2(w3.x, w3.x); wd2[13] = pack2(w3.y, w3.y);
        wd2[14] = pack2(w3.z, w3.z); wd2[15] = pack2(w3.w, w3.w);

        const int j = jc >> 5, c = jc & 31;
        const unsigned base = (unsigned)j * (NIN * CC) + (unsigned)i * CC + (unsigned)c;

        #pragma unroll 1
        for (int h = 0; h < 2; ++h) {            // batch halves: b in [16h, 16h+16)
            unsigned long long acc[8];
            #pragma unroll
            for (int k = 0; k < 8; ++k) acc[k] = 0ULL;

            #pragma unroll 4
            for (int d = 0; d < 16; ++d) {
                const float4* up = reinterpret_cast<const float4*>(u_s + d * 32 + h * 16);
                float4 q0 = up[0], q1 = up[1], q2 = up[2], q3 = up[3];
                acc[0] = ffma2(pack2(q0.x, q0.y), wd2[d], acc[0]);
                acc[1] = ffma2(pack2(q0.z, q0.w), wd2[d], acc[1]);
                acc[2] = ffma2(pack2(q1.x, q1.y), wd2[d], acc[2]);
                acc[3] = ffma2(pack2(q1.z, q1.w), wd2[d], acc[3]);
                acc[4] = ffma2(pack2(q2.x, q2.y), wd2[d], acc[4]);
                acc[5] = ffma2(pack2(q2.z, q2.w), wd2[d], acc[5]);
                acc[6] = ffma2(pack2(q3.x, q3.y), wd2[d], acc[6]);
                acc[7] = ffma2(pack2(q3.z, q3.w), wd2[d], acc[7]);
            }

            #pragma unroll
            for (int k = 0; k < 8; ++k) {
                float fx, fy;
                unpack2(acc[k], fx, fy);
                const unsigned b0 = (unsigned)(h * 16 + 2 * k);
                g_uhat[base + b0 * PLANE]       = __float2half_rn(fx);
                g_uhat[base + (b0 + 1) * PLANE] = __float2half_rn(fy);
            }
        }
    }
}

// =====================================================================
// Phase 2: dynamic routing, 2-CTA cluster per (b,j).
// Each CTA holds 1024 rows of u_hat as fp32 in SMEM (no per-iteration
// cvt), logits in SMEM, and exchanges its partial (Z, s[32]) with the
// peer CTA via DSMEM + barrier.cluster each iteration. Both CTAs
// compute v identically (2-term add is commutative -> bit-identical).
// =====================================================================
#define RT_THREADS 512
#define IH 1024                      // rows per CTA

// smem floats: uh 32768 | bl 1024 | wsum 512 | wz 16 | rs 32 | rz 4 | vv 32
#define SM_UH   0
#define SM_BL   (IH * CC)
#define SM_WSUM (SM_BL + IH)
#define SM_WZ   (SM_WSUM + 16 * 32)
#define SM_RS   (SM_WZ + 16)
#define SM_RZ   (SM_RS + 32)
#define SM_VV   (SM_RZ + 4)
#define RT_SMEM ((SM_VV + 32) * 4)

__device__ __forceinline__ void st_peer_f32(float* p, unsigned peer, float v) {
    unsigned a = (unsigned)__cvta_generic_to_shared(p);
    unsigned r;
    asm("mapa.shared::cluster.u32 %0, %1, %2;" : "=r"(r) : "r"(a), "r"(peer));
    asm volatile("st.shared::cluster.f32 [%0], %1;" :: "r"(r), "f"(v) : "memory");
}
__device__ __forceinline__ void cluster_sync_() {
    asm volatile("barrier.cluster.arrive.aligned;" ::: "memory");
    asm volatile("barrier.cluster.wait.aligned;" ::: "memory");
}

__global__ __launch_bounds__(RT_THREADS, 1) __cluster_dims__(2, 1, 1)
void routing_kernel(float* __restrict__ out) {
    extern __shared__ unsigned char sm_raw[];
    float* smf  = reinterpret_cast<float*>(sm_raw);
    float* uh   = smf + SM_UH;
    float* bl   = smf + SM_BL;
    float* wsum = smf + SM_WSUM;
    float* wz   = smf + SM_WZ;
    float* rs   = smf + SM_RS;
    float* rz   = smf + SM_RZ;
    float* vv   = smf + SM_VV;

    const int tid  = threadIdx.x;
    const int wid  = tid >> 5;
    const int lane = tid & 31;
    unsigned rank;
    asm("mov.u32 %0, %%cluster_ctarank;" : "=r"(rank));
    const unsigned peer = rank ^ 1u;
    const int bj = blockIdx.x >> 1;

    // ---- load 1024 rows fp16 -> fp32 SMEM (chunk-swizzled: phys = k ^ (row&7))
    const uint4* src = reinterpret_cast<const uint4*>(
        g_uhat + ((size_t)bj * NIN + (size_t)rank * IH) * CC);
    #pragma unroll
    for (int t = 0; t < 8; ++t) {
        int m = t * RT_THREADS + tid;          // 4096 fp16 16B-chunks
        int row = m >> 2, k = m & 3, sw = row & 7;
        uint4 q = src[m];
        float2 f0 = __half22float2(*reinterpret_cast<__half2*>(&q.x));
        float2 f1 = __half22float2(*reinterpret_cast<__half2*>(&q.y));
        float2 f2 = __half22float2(*reinterpret_cast<__half2*>(&q.z));
        float2 f3 = __half22float2(*reinterpret_cast<__half2*>(&q.w));
        float4* dst = reinterpret_cast<float4*>(uh + row * 32);
        dst[(2 * k)     ^ sw] = make_float4(f0.x, f0.y, f1.x, f1.y);
        dst[(2 * k + 1) ^ sw] = make_float4(f2.x, f2.y, f3.x, f3.y);
    }
    for (int t = tid; t < IH; t += RT_THREADS) bl[t] = 0.0f;
    __syncthreads();

    unsigned long long vr2[16];   // packed v (c-pairs)

    for (int it = 0; it < NITR; ++it) {
        unsigned long long s2[16];
        #pragma unroll
        for (int m = 0; m < 16; ++m) s2[m] = 0ULL;
        float z = 0.0f;

        #pragma unroll
        for (int t = 0; t < 2; ++t) {
            const int i  = t * RT_THREADS + tid;
            const int sw = i & 7;
            const float4* rowp = reinterpret_cast<const float4*>(uh + i * 32);

            float e;
            if (it == 0) {
                e = 1.0f;                         // softmax(0) -> uniform
            } else {
                unsigned long long d2 = 0ULL;     // pass A: agreement dot
                #pragma unroll
                for (int kk = 0; kk < 8; ++kk) {
                    float4 q = rowp[kk ^ sw];
                    d2 = ffma2(pack2(q.x, q.y), vr2[2 * kk],     d2);
                    d2 = ffma2(pack2(q.z, q.w), vr2[2 * kk + 1], d2);
                }
                float dx, dy;
                unpack2(d2, dx, dy);
                float bn = bl[i] + dx + dy;
                bl[i] = bn;
                e = __expf(bn);                   // no max-shift needed: |b| stays small
            }
            z += e;
            const unsigned long long e2 = pack2(e, e);
            #pragma unroll
            for (int kk = 0; kk < 8; ++kk) {      // pass B: s += e * u_hat_i
                float4 q = rowp[kk ^ sw];
                s2[2 * kk]     = ffma2(pack2(q.x, q.y), e2, s2[2 * kk]);
                s2[2 * kk + 1] = ffma2(pack2(q.z, q.w), e2, s2[2 * kk + 1]);
            }
        }

        // ---- butterfly-SPLIT warp reduction: lane ends with sum for c=lane
        float v[32];
        #pragma unroll
        for (int m = 0; m < 16; ++m) unpack2(s2[m], v[2 * m], v[2 * m + 1]);
        #pragma unroll
        for (int mm = 16; mm >= 1; mm >>= 1) {
            const bool hi = (lane & mm) != 0;
            #pragma unroll
            for (int k = 0; k < mm; ++k) {
                float send = hi ? v[k] : v[k + mm];
                float recv = __shfl_xor_sync(0xffffffffu, send, mm);
                v[k] = (hi ? v[k + mm] : v[k]) + recv;
            }
        }
        #pragma unroll
        for (int o = 16; o; o >>= 1) z += __shfl_xor_sync(0xffffffffu, z, o);

        wsum[wid * 32 + lane] = v[0];
        if (lane == 0) wz[wid] = z;
        __syncthreads();

        // ---- cross-warp combine + DSMEM exchange (warp 0)
        float s_loc = 0.0f, z_loc = 0.0f;
        if (wid == 0) {
            #pragma unroll
            for (int w = 0; w < 16; ++w) s_loc += wsum[w * 32 + lane];
            float zz = (lane < 16) ? wz[lane] : 0.0f;
            #pragma unroll
            for (int o = 16; o; o >>= 1) zz += __shfl_xor_sync(0xffffffffu, zz, o);
            z_loc = zz;
            st_peer_f32(rs + lane, peer, s_loc);
            if (lane == 0) st_peer_f32(rz, peer, z_loc);
        }
        cluster_sync_();

        if (wid == 0) {
            float s_tot = s_loc + rs[lane];
            float z_tot = z_loc + rz[0];
            float s  = s_tot / z_tot;
            float vc = s + 1e-7f;                 // Keras eps
            float nn = vc * vc;
            #pragma unroll
            for (int o = 16; o; o >>= 1) nn += __shfl_xor_sync(0xffffffffu, nn, o);
            float sc = nn / ((1.0f + nn) * sqrtf(nn));   // n/(1+n)/sqrt(n)
            vv[lane] = vc * sc;
        }
        __syncthreads();

        if (it < NITR - 1) {
            const float4* vp = reinterpret_cast<const float4*>(vv);
            #pragma unroll
            for (int kk = 0; kk < 8; ++kk) {
                float4 q = vp[kk];
                vr2[2 * kk]     = pack2(q.x, q.y);
                vr2[2 * kk + 1] = pack2(q.z, q.w);
            }
        }
    }

    if (rank == 0 && wid == 0) out[(size_t)bj * CC + lane] = vv[lane];
}

// =====================================================================
extern "C" void kernel_launch(void* const* d_in, const int* in_sizes, int n_in,
                              void* d_out, int out_size) {
    const float* x = (const float*)d_in[0];
    const float* W = (const float*)d_in[1];
    if (n_in >= 2 && in_sizes[0] > in_sizes[1]) {  // x is the smaller input
        const float* t = x; x = W; W = t;
    }

    cudaFuncSetAttribute(routing_kernel,
                         cudaFuncAttributeMaxDynamicSharedMemorySize, RT_SMEM);

    uhat_kernel<<<NIN, 256>>>(x, W);
    routing_kernel<<<BB * JJ * 2, RT_THREADS, RT_SMEM>>>((float*)d_out);
    (void)out_size;
}

// round 7
// speedup vs baseline: 1.0230x; 1.0230x over previous
#include <cuda_runtime.h>
#include <cuda_fp16.h>

#define BB   32
#define NIN  2048
#define DIN  16
#define JJ   64
#define CC   32
#define NITR 5
#define PLANE 4194304u   // JJ*NIN*CC halfs per batch-plane

typedef unsigned long long ull;

// 256 MB fp16 scratch, layout [b][j][i][c]
__device__ __half g_uhat[(size_t)BB * JJ * NIN * CC];

// ---------- helpers ----------
__device__ __forceinline__ ull pack2(float x, float y) {
    ull r; asm("mov.b64 %0, {%1, %2};" : "=l"(r) : "f"(x), "f"(y)); return r;
}
__device__ __forceinline__ void unpack2(ull v, float& x, float& y) {
    asm("mov.b64 {%0, %1}, %2;" : "=f"(x), "=f"(y) : "l"(v));
}
__device__ __forceinline__ ull ffma2(ull a, ull b, ull c) {
    ull d; asm("fma.rn.f32x2 %0, %1, %2, %3;" : "=l"(d) : "l"(a), "l"(b), "l"(c)); return d;
}
// one LDS.128 -> two u64 regs, no repacking movs
__device__ __forceinline__ void lds2(const void* p, ull& a, ull& b) {
    unsigned ad = (unsigned)__cvta_generic_to_shared(p);
    asm("ld.shared.v2.u64 {%0, %1}, [%2];" : "=l"(a), "=l"(b) : "r"(ad));
}

// =====================================================================
// Phase 1: u_hat[b,i,j,c] = sum_d u[b,d]*W[i,jc,d].  Block per i.
// Thread owns 2 c-quads (4 consecutive c of one j) -> STG.64 stores.
// u pre-packed {u,u} in smem; inner loop = LDS.128 + FFMA2 only.
// =====================================================================
__global__ __launch_bounds__(256, 2) void uhat_kernel(const float* __restrict__ x,
                                                      const float* __restrict__ W) {
    const int i = blockIdx.x, tid = threadIdx.x;

    __shared__ ull u2s[16 * 32];                 // [d][b] = {u,u}
    for (int k = tid; k < 512; k += 256) {
        int d = k >> 5, b = k & 31;
        float v = x[((size_t)b * NIN + i) * DIN + d];
        u2s[d * 32 + b] = pack2(v, v);
    }
    __syncthreads();

    #pragma unroll 1
    for (int qq = 0; qq < 2; ++qq) {
        const int q = (qq << 8) + tid;
        const int j = q >> 3, c0 = (q & 7) << 2;

        float w[64];
        {
            const float4* wr = reinterpret_cast<const float4*>(
                W + ((size_t)i * (JJ * CC) + (size_t)j * CC + c0) * DIN);
            #pragma unroll
            for (int m = 0; m < 16; ++m) *reinterpret_cast<float4*>(w + 4 * m) = wr[m];
        }
        ull wp01[16], wp23[16];
        #pragma unroll
        for (int d = 0; d < 16; ++d) {
            wp01[d] = pack2(w[d],      w[16 + d]);   // {W[c0][d], W[c0+1][d]}
            wp23[d] = pack2(w[32 + d], w[48 + d]);   // {W[c0+2][d], W[c0+3][d]}
        }

        __half* gout = g_uhat + (size_t)j * (NIN * CC) + (size_t)i * CC + c0;

        #pragma unroll 1
        for (int h = 0; h < 4; ++h) {                // 8 batches per chunk
            ull a01[8], a23[8];
            #pragma unroll
            for (int m = 0; m < 8; ++m) { a01[m] = 0ULL; a23[m] = 0ULL; }

            #pragma unroll
            for (int d = 0; d < 16; ++d) {
                const ull* up = u2s + d * 32 + h * 8;
                ull u[8];
                lds2(up,     u[0], u[1]); lds2(up + 2, u[2], u[3]);
                lds2(up + 4, u[4], u[5]); lds2(up + 6, u[6], u[7]);
                #pragma unroll
                for (int m = 0; m < 8; ++m) {
                    a01[m] = ffma2(u[m], wp01[d], a01[m]);
                    a23[m] = ffma2(u[m], wp23[d], a23[m]);
                }
            }
            #pragma unroll
            for (int m = 0; m < 8; ++m) {
                float f0, f1, f2, f3;
                unpack2(a01[m], f0, f1); unpack2(a23[m], f2, f3);
                __half2 h01 = __floats2half2_rn(f0, f1);
                __half2 h23 = __floats2half2_rn(f2, f3);
                uint2 st;
                st.x = *reinterpret_cast<unsigned*>(&h01);
                st.y = *reinterpret_cast<unsigned*>(&h23);
                *reinterpret_cast<uint2*>(gout + (size_t)(h * 8 + m) * PLANE) = st;
            }
        }
    }
}

// =====================================================================
// Phase 2: routing, 2-CTA cluster per (b,j); 1024 fp32 rows per CTA in
// SMEM (chunk-swizzled). Single pass per row per iteration (row held in
// regs); logits in registers; peer exchange via DSMEM + mbarrier.
// =====================================================================
#define RT_THREADS 512
#define IH 1024

// float offsets in smem
#define SM_UH   0
#define SM_WSUM (IH * CC)                // 16*32
#define SM_WZ   (SM_WSUM + 512)          // 16
#define SM_VV   (SM_WZ + 16)             // 32
#define SM_RS   (SM_VV + 32)             // 2 buffers x 34
#define SM_END  (SM_RS + 68)
#define OFF_MBAR (SM_END * 4)            // 8B aligned (SM_END*4 % 8 == 0)
#define RT_SMEM  (OFF_MBAR + 16)

__device__ __forceinline__ void st_peer_f32(const float* p, unsigned peer, float v) {
    unsigned a = (unsigned)__cvta_generic_to_shared(p), r;
    asm("mapa.shared::cluster.u32 %0, %1, %2;" : "=r"(r) : "r"(a), "r"(peer));
    asm volatile("st.shared::cluster.f32 [%0], %1;" :: "r"(r), "f"(v) : "memory");
}
__device__ __forceinline__ void arrive_peer(unsigned mbar, unsigned peer) {
    unsigned r;
    asm("mapa.shared::cluster.u32 %0, %1, %2;" : "=r"(r) : "r"(mbar), "r"(peer));
    asm volatile("mbarrier.arrive.release.cluster.shared::cluster.b64 _, [%0];"
                 :: "r"(r) : "memory");
}
__device__ __forceinline__ void mbar_wait_acq(unsigned a, unsigned parity) {
    asm volatile(
        "{\n\t.reg .pred P;\n"
        "L1_%=:\n\t"
        "mbarrier.try_wait.parity.acquire.cluster.shared::cta.b64 P, [%0], %1;\n\t"
        "@P bra L2_%=;\n\t"
        "bra L1_%=;\n"
        "L2_%=:\n\t}"
        :: "r"(a), "r"(parity) : "memory");
}

__global__ __launch_bounds__(RT_THREADS, 1) __cluster_dims__(2, 1, 1)
void routing_kernel(float* __restrict__ out) {
    extern __shared__ unsigned char sm_raw[];
    float* smf  = reinterpret_cast<float*>(sm_raw);
    float* uh   = smf + SM_UH;
    float* wsum = smf + SM_WSUM;
    float* wz   = smf + SM_WZ;
    float* vv   = smf + SM_VV;
    float* rs   = smf + SM_RS;
    const unsigned mbar = (unsigned)__cvta_generic_to_shared(sm_raw + OFF_MBAR);

    const int tid = threadIdx.x, wid = tid >> 5, lane = tid & 31;
    unsigned rank;
    asm("mov.u32 %0, %%cluster_ctarank;" : "=r"(rank));
    const unsigned peer = rank ^ 1u;
    const int bj = blockIdx.x >> 1;

    if (tid == 0)
        asm volatile("mbarrier.init.shared.b64 [%0], 32;" :: "r"(mbar) : "memory");

    // load 1024 rows fp16 -> fp32 smem, chunk-swizzled (phys chunk = k ^ (row&7))
    const uint4* src = reinterpret_cast<const uint4*>(
        g_uhat + ((size_t)bj * NIN + (size_t)rank * IH) * CC);
    #pragma unroll
    for (int t = 0; t < 8; ++t) {
        int m = t * RT_THREADS + tid;
        int row = m >> 2, k = m & 3, sw = row & 7;
        uint4 qv = src[m];
        float2 f0 = __half22float2(*reinterpret_cast<__half2*>(&qv.x));
        float2 f1 = __half22float2(*reinterpret_cast<__half2*>(&qv.y));
        float2 f2 = __half22float2(*reinterpret_cast<__half2*>(&qv.z));
        float2 f3 = __half22float2(*reinterpret_cast<__half2*>(&qv.w));
        float4* dst = reinterpret_cast<float4*>(uh + row * 32);
        dst[(2 * k)     ^ sw] = make_float4(f0.x, f0.y, f1.x, f1.y);
        dst[(2 * k + 1) ^ sw] = make_float4(f2.x, f2.y, f3.x, f3.y);
    }
    __syncthreads();
    // peer's mbar must be initialized before any remote arrive
    asm volatile("barrier.cluster.arrive.aligned;" ::: "memory");
    asm volatile("barrier.cluster.wait.aligned;" ::: "memory");

    float bl0 = 0.0f, bl1 = 0.0f;    // logits for rows tid, 512+tid
    ull vr2[16];

    for (int it = 0; it < NITR; ++it) {
        ull s2[16];
        #pragma unroll
        for (int m = 0; m < 16; ++m) s2[m] = 0ULL;
        float z = 0.0f;

        #pragma unroll
        for (int t = 0; t < 2; ++t) {
            const int i  = t * RT_THREADS + tid;
            const int sw = i & 7;
            const ull* rp = reinterpret_cast<const ull*>(uh + i * 32);

            ull r[16];
            #pragma unroll
            for (int kk = 0; kk < 8; ++kk)
                lds2(rp + 2 * (kk ^ sw), r[2 * kk], r[2 * kk + 1]);

            float e;
            if (it == 0) {
                e = 1.0f;
            } else {
                ull d2 = 0ULL;
                #pragma unroll
                for (int kk = 0; kk < 16; ++kk) d2 = ffma2(r[kk], vr2[kk], d2);
                float dx, dy;
                unpack2(d2, dx, dy);
                float bn = (t ? bl1 : bl0) + dx + dy;
                if (t) bl1 = bn; else bl0 = bn;
                e = __expf(bn);                     // |b| small: no max-shift needed
            }
            z += e;
            const ull e2 = pack2(e, e);
            #pragma unroll
            for (int kk = 0; kk < 16; ++kk) s2[kk] = ffma2(r[kk], e2, s2[kk]);
        }

        // butterfly-split warp reduction: lane ends with sum for c=lane
        float v[32];
        #pragma unroll
        for (int m = 0; m < 16; ++m) unpack2(s2[m], v[2 * m], v[2 * m + 1]);
        #pragma unroll
        for (int mm = 16; mm >= 1; mm >>= 1) {
            const bool hi = (lane & mm) != 0;
            #pragma unroll
            for (int k = 0; k < mm; ++k) {
                float send = hi ? v[k] : v[k + mm];
                float recv = __shfl_xor_sync(0xffffffffu, send, mm);
                v[k] = (hi ? v[k + mm] : v[k]) + recv;
            }
        }
        #pragma unroll
        for (int o = 16; o; o >>= 1) z += __shfl_xor_sync(0xffffffffu, z, o);

        wsum[wid * 32 + lane] = v[0];
        if (lane == 0) wz[wid] = z;
        __syncthreads();

        if (wid == 0) {
            float s_loc = 0.0f;
            #pragma unroll
            for (int w = 0; w < 16; ++w) s_loc += wsum[w * 32 + lane];
            float zz = (lane < 16) ? wz[lane] : 0.0f;
            #pragma unroll
            for (int o = 16; o; o >>= 1) zz += __shfl_xor_sync(0xffffffffu, zz, o);

            float* buf = rs + (it & 1) * 34;
            st_peer_f32(buf + lane, peer, s_loc);
            if (lane == 0) st_peer_f32(buf + 32, peer, zz);
            arrive_peer(mbar, peer);                 // 32 release-arrives
            mbar_wait_acq(mbar, it & 1);

            float s_tot = s_loc + buf[lane];
            float z_tot = zz + buf[32];
            float s  = s_tot / z_tot;
            float vc = s + 1e-7f;                    // Keras eps
            float nn = vc * vc;
            #pragma unroll
            for (int o = 16; o; o >>= 1) nn += __shfl_xor_sync(0xffffffffu, nn, o);
            float sc = nn / ((1.0f + nn) * sqrtf(nn));
            vv[lane] = vc * sc;
        }
        __syncthreads();

        if (it < NITR - 1) {
            const float4* vp = reinterpret_cast<const float4*>(vv);
            #pragma unroll
            for (int kk = 0; kk < 8; ++kk) {
                float4 qv = vp[kk];
                vr2[2 * kk]     = pack2(qv.x, qv.y);
                vr2[2 * kk + 1] = pack2(qv.z, qv.w);
            }
        }
    }

    if (rank == 0 && wid == 0) out[(size_t)bj * CC + lane] = vv[lane];
}

// =====================================================================
extern "C" void kernel_launch(void* const* d_in, const int* in_sizes, int n_in,
                              void* d_out, int out_size) {
    const float* x = (const float*)d_in[0];
    const float* W = (const float*)d_in[1];
    if (n_in >= 2 && in_sizes[0] > in_sizes[1]) {
        const float* t = x; x = W; W = t;
    }
    cudaFuncSetAttribute(routing_kernel,
                         cudaFuncAttributeMaxDynamicSharedMemorySize, RT_SMEM);
    uhat_kernel<<<NIN, 256>>>(x, W);
    routing_kernel<<<BB * JJ * 2, RT_THREADS, RT_SMEM>>>((float*)d_out);
    (void)out_size;
}

// round 8
// speedup vs baseline: 1.0857x; 1.0612x over previous
#include <cuda_runtime.h>
#include <cuda_fp16.h>

#define BB   32
#define NIN  2048
#define DIN  16
#define JJ   64
#define CC   32
#define NITR 5
#define PLANE 4194304u   // JJ*NIN*CC halfs per batch-plane

typedef unsigned long long ull;

// 256 MB fp16 scratch, layout [b][j][i][c]
__device__ __half g_uhat[(size_t)BB * JJ * NIN * CC];

// ---------- helpers ----------
__device__ __forceinline__ ull pack2(float x, float y) {
    ull r; asm("mov.b64 %0, {%1, %2};" : "=l"(r) : "f"(x), "f"(y)); return r;
}
__device__ __forceinline__ void unpack2(ull v, float& x, float& y) {
    asm("mov.b64 {%0, %1}, %2;" : "=f"(x), "=f"(y) : "l"(v));
}
__device__ __forceinline__ ull ffma2(ull a, ull b, ull c) {
    ull d; asm("fma.rn.f32x2 %0, %1, %2, %3;" : "=l"(d) : "l"(a), "l"(b), "l"(c)); return d;
}
// one LDS.128 -> two u64 regs
__device__ __forceinline__ void lds2(const void* p, ull& a, ull& b) {
    unsigned ad = (unsigned)__cvta_generic_to_shared(p);
    asm("ld.shared.v2.u64 {%0, %1}, [%2];" : "=l"(a), "=l"(b) : "r"(ad));
}

// =====================================================================
// Phase 1 (unchanged from R7): u_hat[b,i,jc] = sum_d u[b,d]*W[i,jc,d]
// =====================================================================
__global__ __launch_bounds__(256, 2) void uhat_kernel(const float* __restrict__ x,
                                                      const float* __restrict__ W) {
    const int i = blockIdx.x, tid = threadIdx.x;

    __shared__ ull u2s[16 * 32];                 // [d][b] = {u,u}
    for (int k = tid; k < 512; k += 256) {
        int d = k >> 5, b = k & 31;
        float v = x[((size_t)b * NIN + i) * DIN + d];
        u2s[d * 32 + b] = pack2(v, v);
    }
    __syncthreads();

    #pragma unroll 1
    for (int qq = 0; qq < 2; ++qq) {
        const int q = (qq << 8) + tid;
        const int j = q >> 3, c0 = (q & 7) << 2;

        float w[64];
        {
            const float4* wr = reinterpret_cast<const float4*>(
                W + ((size_t)i * (JJ * CC) + (size_t)j * CC + c0) * DIN);
            #pragma unroll
            for (int m = 0; m < 16; ++m) *reinterpret_cast<float4*>(w + 4 * m) = wr[m];
        }
        ull wp01[16], wp23[16];
        #pragma unroll
        for (int d = 0; d < 16; ++d) {
            wp01[d] = pack2(w[d],      w[16 + d]);
            wp23[d] = pack2(w[32 + d], w[48 + d]);
        }

        __half* gout = g_uhat + (size_t)j * (NIN * CC) + (size_t)i * CC + c0;

        #pragma unroll 1
        for (int h = 0; h < 4; ++h) {
            ull a01[8], a23[8];
            #pragma unroll
            for (int m = 0; m < 8; ++m) { a01[m] = 0ULL; a23[m] = 0ULL; }

            #pragma unroll
            for (int d = 0; d < 16; ++d) {
                const ull* up = u2s + d * 32 + h * 8;
                ull u[8];
                lds2(up,     u[0], u[1]); lds2(up + 2, u[2], u[3]);
                lds2(up + 4, u[4], u[5]); lds2(up + 6, u[6], u[7]);
                #pragma unroll
                for (int m = 0; m < 8; ++m) {
                    a01[m] = ffma2(u[m], wp01[d], a01[m]);
                    a23[m] = ffma2(u[m], wp23[d], a23[m]);
                }
            }
            #pragma unroll
            for (int m = 0; m < 8; ++m) {
                float f0, f1, f2, f3;
                unpack2(a01[m], f0, f1); unpack2(a23[m], f2, f3);
                __half2 h01 = __floats2half2_rn(f0, f1);
                __half2 h23 = __floats2half2_rn(f2, f3);
                uint2 st;
                st.x = *reinterpret_cast<unsigned*>(&h01);
                st.y = *reinterpret_cast<unsigned*>(&h23);
                *reinterpret_cast<uint2*>(gout + (size_t)(h * 8 + m) * PLANE) = st;
            }
        }
    }
}

// =====================================================================
// Phase 2: routing, 2-CTA cluster per (b,j); 1024 fp32 rows/CTA in SMEM.
// Thread = (row, c-half): holds 8 u64 of row, 8 of s, 8 of v -> no
// spills. One row read per iteration; pair combines dot via shfl.xor 1.
// All warps do the cross-warp combine redundantly; warp0 does the
// DSMEM peer exchange; Z double-count fixed by exact *0.5.
// =====================================================================
#define RT_THREADS 512
#define IH 1024

// float offsets in smem
#define SM_UH   0
#define SM_WSUM (IH * CC)                // 16*32
#define SM_WZ   (SM_WSUM + 512)          // 16
#define SM_VV   (SM_WZ + 16)             // 32
#define SM_RS   (SM_VV + 32)             // 2 buffers x 34
#define SM_END  (SM_RS + 68)
#define OFF_MBAR (SM_END * 4)
#define RT_SMEM  (OFF_MBAR + 16)

__device__ __forceinline__ void st_peer_f32(const float* p, unsigned peer, float v) {
    unsigned a = (unsigned)__cvta_generic_to_shared(p), r;
    asm("mapa.shared::cluster.u32 %0, %1, %2;" : "=r"(r) : "r"(a), "r"(peer));
    asm volatile("st.shared::cluster.f32 [%0], %1;" :: "r"(r), "f"(v) : "memory");
}
__device__ __forceinline__ void arrive_peer(unsigned mbar, unsigned peer) {
    unsigned r;
    asm("mapa.shared::cluster.u32 %0, %1, %2;" : "=r"(r) : "r"(mbar), "r"(peer));
    asm volatile("mbarrier.arrive.release.cluster.shared::cluster.b64 _, [%0];"
                 :: "r"(r) : "memory");
}
__device__ __forceinline__ void mbar_wait_acq(unsigned a, unsigned parity) {
    asm volatile(
        "{\n\t.reg .pred P;\n"
        "L1_%=:\n\t"
        "mbarrier.try_wait.parity.acquire.cluster.shared::cta.b64 P, [%0], %1;\n\t"
        "@P bra L2_%=;\n\t"
        "bra L1_%=;\n"
        "L2_%=:\n\t}"
        :: "r"(a), "r"(parity) : "memory");
}

__global__ __launch_bounds__(RT_THREADS, 1) __cluster_dims__(2, 1, 1)
void routing_kernel(float* __restrict__ out) {
    extern __shared__ unsigned char sm_raw[];
    float* smf  = reinterpret_cast<float*>(sm_raw);
    float* uh   = smf + SM_UH;
    float* wsum = smf + SM_WSUM;
    float* wz   = smf + SM_WZ;
    float* vv   = smf + SM_VV;
    float* rs   = smf + SM_RS;
    const unsigned mbar = (unsigned)__cvta_generic_to_shared(sm_raw + OFF_MBAR);

    const int tid = threadIdx.x, wid = tid >> 5, lane = tid & 31;
    const int half  = tid & 1;          // c-half: [16*half, 16*half+16)
    const int rb    = tid >> 1;         // row base 0..255
    const int hbase = half << 2;        // 16B-chunk base of this half
    unsigned rank;
    asm("mov.u32 %0, %%cluster_ctarank;" : "=r"(rank));
    const unsigned peer = rank ^ 1u;
    const int bj = blockIdx.x >> 1;

    if (tid == 0)
        asm volatile("mbarrier.init.shared.b64 [%0], 32;" :: "r"(mbar) : "memory");

    // load 1024 rows fp16 -> fp32 smem; logical 16B chunk c -> phys c^(row&7)
    const uint4* src = reinterpret_cast<const uint4*>(
        g_uhat + ((size_t)bj * NIN + (size_t)rank * IH) * CC);
    #pragma unroll
    for (int t = 0; t < 8; ++t) {
        int m = t * RT_THREADS + tid;
        int row = m >> 2, k = m & 3, sw = row & 7;
        uint4 qv = src[m];
        float2 f0 = __half22float2(*reinterpret_cast<__half2*>(&qv.x));
        float2 f1 = __half22float2(*reinterpret_cast<__half2*>(&qv.y));
        float2 f2 = __half22float2(*reinterpret_cast<__half2*>(&qv.z));
        float2 f3 = __half22float2(*reinterpret_cast<__half2*>(&qv.w));
        float4* dst = reinterpret_cast<float4*>(uh + row * 32);
        dst[(2 * k)     ^ sw] = make_float4(f0.x, f0.y, f1.x, f1.y);
        dst[(2 * k + 1) ^ sw] = make_float4(f2.x, f2.y, f3.x, f3.y);
    }
    __syncthreads();
    // peer's mbar must be initialized before any remote arrive
    asm volatile("barrier.cluster.arrive.aligned;" ::: "memory");
    asm volatile("barrier.cluster.wait.aligned;" ::: "memory");

    // final-reduction lane -> c mapping (bit-reversed split butterfly)
    const int cidx = (half << 4)
                   | ((lane & 2) ? 8 : 0) | ((lane & 4) ? 4 : 0)
                   | ((lane & 8) ? 2 : 0) | ((lane & 16) ? 1 : 0);

    float blp[4] = {0.f, 0.f, 0.f, 0.f};   // logits (duplicated per pair)
    ull vr2[8];                             // v, this thread's c-half

    for (int it = 0; it < NITR; ++it) {
        ull s2[8];
        #pragma unroll
        for (int m = 0; m < 8; ++m) s2[m] = 0ULL;
        float z = 0.0f;

        #pragma unroll
        for (int p = 0; p < 4; ++p) {
            const int r  = (p << 8) + rb;
            const int sw = r & 7;
            const ull* rp = reinterpret_cast<const ull*>(uh + r * 32);

            ull rr[8];
            #pragma unroll
            for (int k = 0; k < 4; ++k) {
                const int mc = (hbase + k) ^ sw;
                lds2(rp + 2 * mc, rr[2 * k], rr[2 * k + 1]);
            }

            float e;
            if (it == 0) {
                e = 1.0f;
            } else {
                ull d2 = 0ULL;
                #pragma unroll
                for (int kk = 0; kk < 8; ++kk) d2 = ffma2(rr[kk], vr2[kk], d2);
                float dx, dy; unpack2(d2, dx, dy);
                float dh = dx + dy;
                float dfull = dh + __shfl_xor_sync(0xffffffffu, dh, 1);
                float bn = blp[p] + dfull;
                blp[p] = bn;
                e = __expf(bn);              // |b| small: no max-shift needed
            }
            z += e;                           // double-counted per pair; halved later
            const ull e2 = pack2(e, e);
            #pragma unroll
            for (int kk = 0; kk < 8; ++kk) s2[kk] = ffma2(rr[kk], e2, s2[kk]);
        }

        // split butterfly over same-parity lanes: 16 values -> 1 per lane
        float v[16];
        #pragma unroll
        for (int m = 0; m < 8; ++m) unpack2(s2[m], v[2 * m], v[2 * m + 1]);
        #pragma unroll
        for (int st = 0; st < 4; ++st) {
            const int lm = 2 << st;          // lane mask 2,4,8,16
            const int mm = 8 >> st;          // surviving half-size 8,4,2,1
            const bool hi = (lane & lm) != 0;
            #pragma unroll
            for (int k = 0; k < 8; ++k) {
                if (k < mm) {
                    float send = hi ? v[k] : v[k + mm];
                    float recv = __shfl_xor_sync(0xffffffffu, send, lm);
                    v[k] = (hi ? v[k + mm] : v[k]) + recv;
                }
            }
        }
        #pragma unroll
        for (int o = 16; o; o >>= 1) z += __shfl_xor_sync(0xffffffffu, z, o);

        wsum[wid * 32 + cidx] = v[0];
        if (lane == 0) wz[wid] = z;
        __syncthreads();

        // all warps combine redundantly (no idle warp0-only phase)
        float s_loc = 0.0f;
        #pragma unroll
        for (int w = 0; w < 16; ++w) s_loc += wsum[w * 32 + lane];
        float zz = (lane < 16) ? wz[lane] : 0.0f;
        #pragma unroll
        for (int o = 16; o; o >>= 1) zz += __shfl_xor_sync(0xffffffffu, zz, o);

        float* buf = rs + (it & 1) * 34;
        if (wid == 0) {
            st_peer_f32(buf + lane, peer, s_loc);
            if (lane == 0) st_peer_f32(buf + 32, peer, zz);
            arrive_peer(mbar, peer);
        }
        mbar_wait_acq(mbar, it & 1);

        float s_tot = s_loc + buf[lane];
        float z_tot = (zz + buf[32]) * 0.5f;   // exact un-double-count
        float s  = s_tot / z_tot;
        float vc = s + 1e-7f;                   // Keras eps
        float nn = vc * vc;
        #pragma unroll
        for (int o = 16; o; o >>= 1) nn += __shfl_xor_sync(0xffffffffu, nn, o);
        float sc = nn / ((1.0f + nn) * sqrtf(nn));
        float vfin = vc * sc;                   // v for c = lane (per warp)

        vv[lane] = vfin;                        // all warps write identical data
        __syncwarp();
        if (it < NITR - 1) {
            const ull* vp = reinterpret_cast<const ull*>(vv) + (half << 3);
            lds2(vp,     vr2[0], vr2[1]); lds2(vp + 2, vr2[2], vr2[3]);
            lds2(vp + 4, vr2[4], vr2[5]); lds2(vp + 6, vr2[6], vr2[7]);
        }
        __syncthreads();                        // protect wsum reuse next iter
    }

    if (rank == 0 && wid == 0) out[(size_t)bj * CC + lane] = vv[lane];
}

// =====================================================================
extern "C" void kernel_launch(void* const* d_in, const int* in_sizes, int n_in,
                              void* d_out, int out_size) {
    const float* x = (const float*)d_in[0];
    const float* W = (const float*)d_in[1];
    if (n_in >= 2 && in_sizes[0] > in_sizes[1]) {
        const float* t = x; x = W; W = t;
    }
    cudaFuncSetAttribute(routing_kernel,
                         cudaFuncAttributeMaxDynamicSharedMemorySize, RT_SMEM);
    uhat_kernel<<<NIN, 256>>>(x, W);
    routing_kernel<<<BB * JJ * 2, RT_THREADS, RT_SMEM>>>((float*)d_out);
    (void)out_size;
}

// round 12
// speedup vs baseline: 1.1096x; 1.0220x over previous
#include <cuda_runtime.h>
#include <cuda_fp16.h>

#define BB   32
#define NIN  2048
#define DIN  16
#define JJ   64
#define CC   32
#define NITR 5
#define PLANE 4194304u   // JJ*NIN*CC halfs per batch-plane

typedef unsigned long long ull;

// 256 MB fp16 scratch, layout [b][j][i][c]
__device__ __half g_uhat[(size_t)BB * JJ * NIN * CC];

// ---------- helpers ----------
__device__ __forceinline__ ull pack2(float x, float y) {
    ull r; asm("mov.b64 %0, {%1, %2};" : "=l"(r) : "f"(x), "f"(y)); return r;
}
__device__ __forceinline__ void unpack2(ull v, float& x, float& y) {
    asm("mov.b64 {%0, %1}, %2;" : "=f"(x), "=f"(y) : "l"(v));
}
__device__ __forceinline__ ull ffma2(ull a, ull b, ull c) {
    ull d; asm("fma.rn.f32x2 %0, %1, %2, %3;" : "=l"(d) : "l"(a), "l"(b), "l"(c)); return d;
}
// one LDS.128 -> two u64 regs
__device__ __forceinline__ void lds2(const void* p, ull& a, ull& b) {
    unsigned ad = (unsigned)__cvta_generic_to_shared(p);
    asm("ld.shared.v2.u64 {%0, %1}, [%2];" : "=l"(a), "=l"(b) : "r"(ad));
}

// =====================================================================
// Phase 1 (unchanged): u_hat[b,i,jc] = sum_d u[b,d]*W[i,jc,d]
// =====================================================================
__global__ __launch_bounds__(256, 2) void uhat_kernel(const float* __restrict__ x,
                                                      const float* __restrict__ W) {
    const int i = blockIdx.x, tid = threadIdx.x;

    __shared__ ull u2s[16 * 32];                 // [d][b] = {u,u}
    for (int k = tid; k < 512; k += 256) {
        int d = k >> 5, b = k & 31;
        float v = x[((size_t)b * NIN + i) * DIN + d];
        u2s[d * 32 + b] = pack2(v, v);
    }
    __syncthreads();

    #pragma unroll 1
    for (int qq = 0; qq < 2; ++qq) {
        const int q = (qq << 8) + tid;
        const int j = q >> 3, c0 = (q & 7) << 2;

        float w[64];
        {
            const float4* wr = reinterpret_cast<const float4*>(
                W + ((size_t)i * (JJ * CC) + (size_t)j * CC + c0) * DIN);
            #pragma unroll
            for (int m = 0; m < 16; ++m) *reinterpret_cast<float4*>(w + 4 * m) = wr[m];
        }
        ull wp01[16], wp23[16];
        #pragma unroll
        for (int d = 0; d < 16; ++d) {
            wp01[d] = pack2(w[d],      w[16 + d]);
            wp23[d] = pack2(w[32 + d], w[48 + d]);
        }

        __half* gout = g_uhat + (size_t)j * (NIN * CC) + (size_t)i * CC + c0;

        #pragma unroll 1
        for (int h = 0; h < 4; ++h) {
            ull a01[8], a23[8];
            #pragma unroll
            for (int m = 0; m < 8; ++m) { a01[m] = 0ULL; a23[m] = 0ULL; }

            #pragma unroll
            for (int d = 0; d < 16; ++d) {
                const ull* up = u2s + d * 32 + h * 8;
                ull u[8];
                lds2(up,     u[0], u[1]); lds2(up + 2, u[2], u[3]);
                lds2(up + 4, u[4], u[5]); lds2(up + 6, u[6], u[7]);
                #pragma unroll
                for (int m = 0; m < 8; ++m) {
                    a01[m] = ffma2(u[m], wp01[d], a01[m]);
                    a23[m] = ffma2(u[m], wp23[d], a23[m]);
                }
            }
            #pragma unroll
            for (int m = 0; m < 8; ++m) {
                float f0, f1, f2, f3;
                unpack2(a01[m], f0, f1); unpack2(a23[m], f2, f3);
                __half2 h01 = __floats2half2_rn(f0, f1);
                __half2 h23 = __floats2half2_rn(f2, f3);
                uint2 st;
                st.x = *reinterpret_cast<unsigned*>(&h01);
                st.y = *reinterpret_cast<unsigned*>(&h23);
                *reinterpret_cast<uint2*>(gout + (size_t)(h * 8 + m) * PLANE) = st;
            }
        }
    }
}

// =====================================================================
// Phase 2: routing, 4-CTA cluster per (b,j); 512 fp32 rows/CTA (64 KB)
// -> 2 CTAs resident per SM so reduction/exchange tails of one CTA hide
// under the other's main loop. Thread = (row, c-half), 4 row-units each.
// 4-way partial all-gather via DSMEM (rank-ordered deterministic sum).
// =====================================================================
#define RT_THREADS 256
#define CLUST 4
#define IH2 512                          // rows per CTA

// float offsets in smem
#define SM_UH   0                        // 512*32 = 16384 floats (64 KB)
#define SM_WSUM (IH2 * CC)               // 8*32
#define SM_WZ   (SM_WSUM + 256)         // 8
#define SM_VV   (SM_WZ + 8)             // 32
#define SM_RS   (SM_VV + 32)            // 2 parities x 4 ranks x 34
#define SM_END  (SM_RS + 272)
#define OFF_MBAR (SM_END * 4)           // byte offset, 8-aligned
#define RT_SMEM  (OFF_MBAR + 16)

__device__ __forceinline__ void st_peer_f32(const float* p, unsigned peer, float v) {
    unsigned a = (unsigned)__cvta_generic_to_shared(p), r;
    asm("mapa.shared::cluster.u32 %0, %1, %2;" : "=r"(r) : "r"(a), "r"(peer));
    asm volatile("st.shared::cluster.f32 [%0], %1;" :: "r"(r), "f"(v) : "memory");
}
__device__ __forceinline__ void arrive_peer(unsigned mbar, unsigned peer) {
    unsigned r;
    asm("mapa.shared::cluster.u32 %0, %1, %2;" : "=r"(r) : "r"(mbar), "r"(peer));
    asm volatile("mbarrier.arrive.release.cluster.shared::cluster.b64 _, [%0];"
                 :: "r"(r) : "memory");
}
__device__ __forceinline__ void mbar_wait_acq(unsigned a, unsigned parity) {
    asm volatile(
        "{\n\t.reg .pred P;\n"
        "L1_%=:\n\t"
        "mbarrier.try_wait.parity.acquire.cluster.shared::cta.b64 P, [%0], %1;\n\t"
        "@P bra L2_%=;\n\t"
        "bra L1_%=;\n"
        "L2_%=:\n\t}"
        :: "r"(a), "r"(parity) : "memory");
}

__global__ __launch_bounds__(RT_THREADS) __cluster_dims__(CLUST, 1, 1)
void routing_kernel(float* __restrict__ out) {
    extern __shared__ unsigned char sm_raw[];
    float* smf  = reinterpret_cast<float*>(sm_raw);
    float* uh   = smf + SM_UH;
    float* wsum = smf + SM_WSUM;
    float* wz   = smf + SM_WZ;
    float* vv   = smf + SM_VV;
    float* rs   = smf + SM_RS;
    const unsigned mbar = (unsigned)__cvta_generic_to_shared(sm_raw + OFF_MBAR);

    const int tid = threadIdx.x, wid = tid >> 5, lane = tid & 31;
    const int half  = tid & 1;          // c-half: [16*half, 16*half+16)
    const int rb    = tid >> 1;         // row base 0..127
    const int hbase = half << 2;        // 16B-chunk base of this half
    unsigned rank;
    asm("mov.u32 %0, %%cluster_ctarank;" : "=r"(rank));
    const int bj = blockIdx.x >> 2;

    if (tid == 0)   // 3 peers x 1 warp x 32 lanes arrive each iteration
        asm volatile("mbarrier.init.shared.b64 [%0], 96;" :: "r"(mbar) : "memory");

    // load 512 rows fp16 -> fp32 smem; logical 16B chunk c -> phys c^(row&7)
    const uint4* src = reinterpret_cast<const uint4*>(
        g_uhat + ((size_t)bj * NIN + (size_t)rank * IH2) * CC);
    #pragma unroll
    for (int t = 0; t < 8; ++t) {
        int m = t * RT_THREADS + tid;       // 2048 16B-chunks
        int row = m >> 2, k = m & 3, sw = row & 7;
        uint4 qv = src[m];
        float2 f0 = __half22float2(*reinterpret_cast<__half2*>(&qv.x));
        float2 f1 = __half22float2(*reinterpret_cast<__half2*>(&qv.y));
        float2 f2 = __half22float2(*reinterpret_cast<__half2*>(&qv.z));
        float2 f3 = __half22float2(*reinterpret_cast<__half2*>(&qv.w));
        float4* dst = reinterpret_cast<float4*>(uh + row * 32);
        dst[(2 * k)     ^ sw] = make_float4(f0.x, f0.y, f1.x, f1.y);
        dst[(2 * k + 1) ^ sw] = make_float4(f2.x, f2.y, f3.x, f3.y);
    }
    __syncthreads();
    // peer mbars must be initialized before any remote arrive
    asm volatile("barrier.cluster.arrive.aligned;" ::: "memory");
    asm volatile("barrier.cluster.wait.aligned;" ::: "memory");

    // final-reduction lane -> c mapping (bit-reversed split butterfly)
    const int cidx = (half << 4)
                   | ((lane & 2) ? 8 : 0) | ((lane & 4) ? 4 : 0)
                   | ((lane & 8) ? 2 : 0) | ((lane & 16) ? 1 : 0);

    float blp[4] = {0.f, 0.f, 0.f, 0.f};   // logits (duplicated per lane pair)
    ull vr2[8];                             // v, this thread's c-half

    for (int it = 0; it < NITR; ++it) {
        ull s2[8];
        #pragma unroll
        for (int m = 0; m < 8; ++m) s2[m] = 0ULL;
        float z = 0.0f;

        #pragma unroll
        for (int p = 0; p < 4; ++p) {
            const int r  = (p << 7) + rb;
            const int sw = r & 7;
            const ull* rp = reinterpret_cast<const ull*>(uh + r * 32);

            ull rr[8];
            #pragma unroll
            for (int k = 0; k < 4; ++k) {
                const int mc = (hbase + k) ^ sw;
                lds2(rp + 2 * mc, rr[2 * k], rr[2 * k + 1]);
            }

            float e;
            if (it == 0) {
                e = 1.0f;
            } else {
                ull d2 = 0ULL;
                #pragma unroll
                for (int kk = 0; kk < 8; ++kk) d2 = ffma2(rr[kk], vr2[kk], d2);
                float dx, dy; unpack2(d2, dx, dy);
                float dh = dx + dy;
                float dfull = dh + __shfl_xor_sync(0xffffffffu, dh, 1);
                float bn = blp[p] + dfull;
                blp[p] = bn;
                e = __expf(bn);              // |b| small: no max-shift needed
            }
            z += e;                           // pair double-count; halved later
            const ull e2 = pack2(e, e);
            #pragma unroll
            for (int kk = 0; kk < 8; ++kk) s2[kk] = ffma2(rr[kk], e2, s2[kk]);
        }

        // split butterfly over same-parity lanes: 16 values -> 1 per lane
        float v[16];
        #pragma unroll
        for (int m = 0; m < 8; ++m) unpack2(s2[m], v[2 * m], v[2 * m + 1]);
        #pragma unroll
        for (int st = 0; st < 4; ++st) {
            const int lm = 2 << st;          // lane mask 2,4,8,16
            const int mm = 8 >> st;          // surviving half-size 8,4,2,1
            const bool hi = (lane & lm) != 0;
            #pragma unroll
            for (int k = 0; k < 8; ++k) {
                if (k < mm) {
                    float send = hi ? v[k] : v[k + mm];
                    float recv = __shfl_xor_sync(0xffffffffu, send, lm);
                    v[k] = (hi ? v[k + mm] : v[k]) + recv;
                }
            }
        }
        #pragma unroll
        for (int o = 16; o; o >>= 1) z += __shfl_xor_sync(0xffffffffu, z, o);

        wsum[wid * 32 + cidx] = v[0];
        if (lane == 0) wz[wid] = z;
        __syncthreads();

        // all 8 warps combine redundantly
        float s_loc = 0.0f;
        #pragma unroll
        for (int w = 0; w < 8; ++w) s_loc += wsum[w * 32 + lane];
        float zz = (lane < 8) ? wz[lane] : 0.0f;
        #pragma unroll
        for (int o = 16; o; o >>= 1) zz += __shfl_xor_sync(0xffffffffu, zz, o);

        // 4-way all-gather of (s_loc[32], zz): warp w -> peer (rank+1+w)&3
        float* bufb = rs + (it & 1) * (4 * 34);
        if (wid < 3) {
            unsigned p = (rank + 1 + (unsigned)wid) & 3u;
            st_peer_f32(bufb + rank * 34 + lane, p, s_loc);
            if (lane == 0) st_peer_f32(bufb + rank * 34 + 32, p, zz);
            arrive_peer(mbar, p);
        }
        mbar_wait_acq(mbar, it & 1);

        // fixed rank-order sum: bit-identical in all 4 CTAs, deterministic
        float s_tot = 0.0f, z_tot = 0.0f;
        #pragma unroll
        for (int r = 0; r < 4; ++r) {
            float sv = (r == (int)rank) ? s_loc : bufb[r * 34 + lane];
            float zv = (r == (int)rank) ? zz    : bufb[r * 34 + 32];
            s_tot += sv;
            z_tot += zv;
        }
        z_tot *= 0.5f;                       // exact un-double-count

        float s  = s_tot / z_tot;
        float vc = s + 1e-7f;                // Keras eps
        float nn = vc * vc;
        #pragma unroll
        for (int o = 16; o; o >>= 1) nn += __shfl_xor_sync(0xffffffffu, nn, o);
        float sc = nn / ((1.0f + nn) * sqrtf(nn));
        float vfin = vc * sc;                // v for c = lane (per warp)

        vv[lane] = vfin;                     // all warps write identical data
        __syncwarp();
        if (it < NITR - 1) {
            const ull* vp = reinterpret_cast<const ull*>(vv) + (half << 3);
            lds2(vp,     vr2[0], vr2[1]); lds2(vp + 2, vr2[2], vr2[3]);
            lds2(vp + 4, vr2[4], vr2[5]); lds2(vp + 6, vr2[6], vr2[7]);
        }
        __syncthreads();                     // protect wsum/rs reuse next iter
    }

    if (rank == 0 && wid == 0) out[(size_t)bj * CC + lane] = vv[lane];
}

// =====================================================================
extern "C" void kernel_launch(void* const* d_in, const int* in_sizes, int n_in,
                              void* d_out, int out_size) {
    const float* x = (const float*)d_in[0];
    const float* W = (const float*)d_in[1];
    if (n_in >= 2 && in_sizes[0] > in_sizes[1]) {
        const float* t = x; x = W; W = t;
    }
    cudaFuncSetAttribute(routing_kernel,
                         cudaFuncAttributeMaxDynamicSharedMemorySize, RT_SMEM);
    uhat_kernel<<<NIN, 256>>>(x, W);
    routing_kernel<<<BB * JJ * CLUST, RT_THREADS, RT_SMEM>>>((float*)d_out);
    (void)out_size;
}